// round 6
// baseline (speedup 1.0000x reference)
#include <cuda_runtime.h>
#include <cstdint>

#define NMAX 200000
#define EMAX 400000
#define DD 128
#define HH 4
#define GDIM 148

typedef unsigned int uint;
typedef unsigned char uchar;

// ---------------- scratch (device globals; no allocation) ----------------
__device__ __align__(16) float g_h[NMAX*DD];          // final-layer h (for pool)
__device__ __align__(16) uint  g_hq[NMAX*64];         // per node: 32 hi uints + 32 lo uints (int8)
__device__ float g_hs[NMAX];                           // per-node quant scale
__device__ __align__(16) float g_xl[NMAX*DD];
__device__ __align__(16) float g_xr[NMAX*DD];
__device__ __align__(16) float g_efull[(EMAX+NMAX)*HH];
__device__ __align__(16) float g_sums[NMAX*HH];
__device__ int g_deg[NMAX];
__device__ int g_off[NMAX+1];
__device__ int g_cur[NMAX];
__device__ int g_eid[EMAX+NMAX];
__device__ int g_bsum[260];

__device__ __forceinline__ void red4(float* p, float a, float b, float c, float d){
    asm volatile("red.global.add.v4.f32 [%0], {%1,%2,%3,%4};"
                 :: "l"(p), "f"(a), "f"(b), "f"(c), "f"(d) : "memory");
}

__device__ __forceinline__ int q8(float v){
    int i = __float2int_rn(v);
    return max(-127, min(127, i));
}

// ---------------- atom encoder + quantize ----------------
__global__ void k_atom(const float* __restrict__ tab, const int* __restrict__ x, int n){
    int i = blockIdx.x;
    int d = threadIdx.x;        // 128 threads
    __shared__ int xf[9];
    __shared__ float wmax[4];
    __shared__ uint u_hi[32], u_lo[32];
    if (d < 9) xf[d] = x[i*9 + d];
    __syncthreads();
    float s = 0.f;
#pragma unroll
    for (int f = 0; f < 9; ++f)
        s += tab[(f*16 + xf[f])*DD + d];

    int lane = d & 31, wid = d >> 5;
    float m = fabsf(s);
#pragma unroll
    for (int o = 16; o > 0; o >>= 1) m = fmaxf(m, __shfl_xor_sync(0xffffffffu, m, o));
    if (lane == 0) wmax[wid] = m;
    __syncthreads();
    m = fmaxf(fmaxf(wmax[0], wmax[1]), fmaxf(wmax[2], wmax[3]));
    float sa = fmaxf(m, 1e-20f) * (1.0f/127.0f);
    float q  = s / sa;
    int   hi = q8(q);
    int   lo = q8((q - (float)hi) * 256.0f);
    ((uchar*)u_hi)[d] = (uchar)hi;
    ((uchar*)u_lo)[d] = (uchar)lo;
    __syncthreads();
    if (d < 32)      g_hq[(size_t)i*64 + d]          = u_hi[d];
    else if (d < 64) g_hq[(size_t)i*64 + 32 + (d-32)] = u_lo[d-32];
    if (d == 0) g_hs[i] = sa;
}

__global__ void k_zero(int n){
    int i = blockIdx.x*blockDim.x + threadIdx.x;
    if (i >= n) return;
    g_deg[i] = 0;
    *(float4*)(g_sums + i*4) = make_float4(0.f,0.f,0.f,0.f);
}

__global__ void k_edge(const float* __restrict__ bond, const int* __restrict__ ei,
                       const int* __restrict__ ea, int E_){
    int e = blockIdx.x*blockDim.x + threadIdx.x;
    if (e >= E_) return;
    int tt  = ea[e];
    int dst = ei[E_ + e];
    float4 b = *(const float4*)(bond + tt*4);
    *(float4*)(g_efull + e*4) = b;
    red4(g_sums + dst*4, b.x, b.y, b.z, b.w);
    atomicAdd(g_deg + dst, 1);
}

__global__ void k_self(int E_, int n){
    int i = blockIdx.x*blockDim.x + threadIdx.x;
    if (i >= n) return;
    float inv = 1.0f / fmaxf((float)g_deg[i], 1.0f);
    float4 s = *(const float4*)(g_sums + i*4);
    *(float4*)(g_efull + (E_ + i)*4) = make_float4(s.x*inv, s.y*inv, s.z*inv, s.w*inv);
}

// ---------------- CSR build ----------------
__global__ void k_scan1(int n){
    __shared__ int ws[8];
    int t = threadIdx.x, b = blockIdx.x;
    int base = b*1024 + t*4;
    int v[4];
#pragma unroll
    for (int j = 0; j < 4; ++j){
        int i = base + j;
        v[j] = (i < n) ? (g_deg[i] + 1) : 0;
    }
    int s = v[0] + v[1] + v[2] + v[3];
    int lane = t & 31, wid = t >> 5;
    int x = s;
#pragma unroll
    for (int o = 1; o < 32; o <<= 1){
        int y = __shfl_up_sync(0xffffffffu, x, o);
        if (lane >= o) x += y;
    }
    if (lane == 31) ws[wid] = x;
    __syncthreads();
    if (t == 0){
        int r = 0;
#pragma unroll
        for (int w = 0; w < 8; ++w){ int tmp = ws[w]; ws[w] = r; r += tmp; }
        g_bsum[b] = r;
    }
    __syncthreads();
    int run = x - s + ws[wid];
#pragma unroll
    for (int j = 0; j < 4; ++j){
        int i = base + j;
        if (i < n) g_off[i] = run;
        run += v[j];
    }
}

__global__ void k_scan2(int nb){
    int r = 0;
    for (int b = 0; b < nb; ++b){ int t = g_bsum[b]; g_bsum[b] = r; r += t; }
    g_bsum[nb] = r;
}

__global__ void k_scan3(int n, int nb){
    int i = blockIdx.x*blockDim.x + threadIdx.x;
    if (i == 0) g_off[n] = g_bsum[nb];
    if (i >= n) return;
    int o = g_off[i] + g_bsum[i >> 10];
    g_off[i] = o;
    g_cur[i] = o;
}

__global__ void k_scatter(const int* __restrict__ ei, int E_, int n){
    int e = blockIdx.x*blockDim.x + threadIdx.x;
    if (e >= E_ + n) return;
    int dst = (e < E_) ? ei[E_ + e] : (e - E_);
    int pos = atomicAdd(g_cur + dst, 1);
    g_eid[pos] = e;
}

// ---------------- int8 2-scale dual GEMM: [xl|xr] = h @ [Wl|Wr] + bias ----------------
// A,B quantized to int8 hi + int8 lo(x256). 3 IMMA terms: hh -> accH, hl+lh -> accX.
// out = (accH + accX/256)*sa*sb + bias.  mma.sync m16n8k32.s8, CTA tile 64x256.
#define SAU 36  // uint row stride per plane (bank-conflict-free: (4*gq+tg) distinct)
#define IMMA(acc, a0,a1,a2,a3, b0,b1) \
    asm volatile("mma.sync.aligned.m16n8k32.row.col.s32.s8.s8.s32 " \
        "{%0,%1,%2,%3}, {%4,%5,%6,%7}, {%8,%9}, {%0,%1,%2,%3};" \
        : "+r"(acc[0]), "+r"(acc[1]), "+r"(acc[2]), "+r"(acc[3]) \
        : "r"(a0), "r"(a1), "r"(a2), "r"(a3), "r"(b0), "r"(b1))

__global__ __launch_bounds__(256, 1)
void k_tc(const float* __restrict__ Wl, const float* __restrict__ bl,
          const float* __restrict__ Wr, const float* __restrict__ br, int n){
    extern __shared__ uint smu[];
    uint* sAh = smu;                    // [64][SAU]
    uint* sAl = sAh + 64*SAU;
    uint* sBh = sAl + 64*SAU;           // [256][SAU]
    uint* sBl = sBh + 256*SAU;
    float* sBs   = (float*)(sBl + 256*SAU);  // [256] col scales
    float* sBias = sBs + 256;                // [256]
    int tid = threadIdx.x, wid = tid >> 5, lane = tid & 31;
    int gq = lane >> 2, tg = lane & 3;
    int wm = wid & 1, wn = wid >> 1;

    // quantize B: one column per thread (coalesced over threads per k)
    {
        int c = tid;
        const float* wp = (c < 128) ? (Wl + c) : (Wr + (c - 128));
        float m = 0.f;
#pragma unroll 8
        for (int k = 0; k < 128; ++k) m = fmaxf(m, fabsf(wp[k*DD]));
        float sb = fmaxf(m, 1e-20f) * (1.0f/127.0f);
        sBs[c] = sb;
        float is = 1.0f / sb;
        for (int kq = 0; kq < 32; ++kq){
            uint hiu = 0, lou = 0;
#pragma unroll
            for (int j = 0; j < 4; ++j){
                float q = wp[(kq*4 + j)*DD] * is;
                int hi = q8(q);
                int lo = q8((q - (float)hi) * 256.0f);
                hiu |= (uint)(hi & 255) << (8*j);
                lou |= (uint)(lo & 255) << (8*j);
            }
            sBh[c*SAU + kq] = hiu;
            sBl[c*SAU + kq] = lou;
        }
        sBias[tid] = (tid < 128) ? bl[tid] : br[tid - 128];
    }

    int tiles = (n + 63) >> 6;
    uint4 pre[4];
    {
        int base = blockIdx.x * 64;
#pragma unroll
        for (int r = 0; r < 4; ++r){
            int j = r*256 + tid;
            int node = j >> 4, p = (j & 15)*4;
            int gn = base + node;
            pre[r] = (gn < n) ? *(const uint4*)(g_hq + (size_t)gn*64 + p)
                              : make_uint4(0u,0u,0u,0u);
        }
    }

    for (int tile = blockIdx.x; tile < tiles; tile += GDIM){
        __syncthreads();
#pragma unroll
        for (int r = 0; r < 4; ++r){
            int j = r*256 + tid;
            int node = j >> 4, p = j & 15;
            uint* dst = (p < 8) ? (sAh + node*SAU + p*4) : (sAl + node*SAU + (p-8)*4);
            *(uint4*)dst = pre[r];
        }
        __syncthreads();
        if (tile + GDIM < tiles){
            int base = (tile + GDIM) * 64;
#pragma unroll
            for (int r = 0; r < 4; ++r){
                int j = r*256 + tid;
                int node = j >> 4, p = (j & 15)*4;
                int gn = base + node;
                pre[r] = (gn < n) ? *(const uint4*)(g_hq + (size_t)gn*64 + p)
                                  : make_uint4(0u,0u,0u,0u);
            }
        }

        int accH[2][8][4], accX[2][8][4];
#pragma unroll
        for (int mb = 0; mb < 2; ++mb)
#pragma unroll
            for (int nb = 0; nb < 8; ++nb)
#pragma unroll
                for (int j = 0; j < 4; ++j){ accH[mb][nb][j] = 0; accX[mb][nb][j] = 0; }

#pragma unroll
        for (int kc = 0; kc < 4; ++kc){
            int k0 = kc*8 + tg;
            uint ah[2][4], al[2][4];
#pragma unroll
            for (int mb = 0; mb < 2; ++mb){
                int r0 = wm*32 + mb*16 + gq;
                ah[mb][0] = sAh[r0*SAU + k0];     ah[mb][1] = sAh[(r0+8)*SAU + k0];
                ah[mb][2] = sAh[r0*SAU + k0 + 4]; ah[mb][3] = sAh[(r0+8)*SAU + k0 + 4];
                al[mb][0] = sAl[r0*SAU + k0];     al[mb][1] = sAl[(r0+8)*SAU + k0];
                al[mb][2] = sAl[r0*SAU + k0 + 4]; al[mb][3] = sAl[(r0+8)*SAU + k0 + 4];
            }
#pragma unroll
            for (int nb = 0; nb < 8; ++nb){
                int col = wn*64 + nb*8 + gq;
                uint bh0 = sBh[col*SAU + k0], bh1 = sBh[col*SAU + k0 + 4];
                uint bl0 = sBl[col*SAU + k0], bl1 = sBl[col*SAU + k0 + 4];
#pragma unroll
                for (int mb = 0; mb < 2; ++mb){
                    IMMA(accH[mb][nb], ah[mb][0],ah[mb][1],ah[mb][2],ah[mb][3], bh0,bh1);
                    IMMA(accX[mb][nb], ah[mb][0],ah[mb][1],ah[mb][2],ah[mb][3], bl0,bl1);
                    IMMA(accX[mb][nb], al[mb][0],al[mb][1],al[mb][2],al[mb][3], bh0,bh1);
                }
            }
        }

        int base = tile*64;
#pragma unroll
        for (int mb = 0; mb < 2; ++mb){
            int gm0 = base + wm*32 + mb*16 + gq;
            int gm1 = gm0 + 8;
            float sa0 = (gm0 < n) ? g_hs[gm0] : 0.f;
            float sa1 = (gm1 < n) ? g_hs[gm1] : 0.f;
#pragma unroll
            for (int nb = 0; nb < 8; ++nb){
                int c0 = wn*64 + nb*8 + tg*2;
                float sb0 = sBs[c0], sb1 = sBs[c0+1];
                float bx = sBias[c0], by = sBias[c0+1];
                float* outp = (c0 < 128) ? g_xl : g_xr;
                int cl = (c0 < 128) ? c0 : c0 - 128;
                if (gm0 < n){
                    float v0 = ((float)accH[mb][nb][0] + (float)accX[mb][nb][0]*0.00390625f)*sa0*sb0 + bx;
                    float v1 = ((float)accH[mb][nb][1] + (float)accX[mb][nb][1]*0.00390625f)*sa0*sb1 + by;
                    *(float2*)(outp + (size_t)gm0*DD + cl) = make_float2(v0, v1);
                }
                if (gm1 < n){
                    float v2 = ((float)accH[mb][nb][2] + (float)accX[mb][nb][2]*0.00390625f)*sa1*sb0 + bx;
                    float v3 = ((float)accH[mb][nb][3] + (float)accX[mb][nb][3]*0.00390625f)*sa1*sb1 + by;
                    *(float2*)(outp + (size_t)gm1*DD + cl) = make_float2(v2, v3);
                }
            }
        }
    }
}

// ---------------- CSR fused edge pass + normalize + bias + relu + quantize ----------------
__global__ void k_att2(const int* __restrict__ ei, const float* __restrict__ We,
                       const float* __restrict__ att, const float* __restrict__ cb,
                       int E_, int n, int last){
    __shared__ float sWe[4*DD];
    __shared__ float sAtt[DD];
    __shared__ float sCb[DD];
    int t = threadIdx.x;
    for (int i = t; i < 4*DD; i += 256) sWe[i] = We[i];
    if (t < DD){ sAtt[t] = att[t]; sCb[t] = cb[t]; }
    __syncthreads();

    int d = blockIdx.x*8 + (t >> 5);
    if (d >= n) return;
    int lane = t & 31;
    int off0 = g_off[d], off1 = g_off[d+1];
    int c0 = lane*4;

    float4 b4 = *(const float4*)(g_xr + (size_t)d*DD + c0);
    float acc0 = 0.f, acc1 = 0.f, acc2 = 0.f, acc3 = 0.f;
    float zacc = 0.f;

    for (int jb = off0; jb < off1; jb += 32){
        int m = min(32, off1 - jb);
        int idx = 0, src = d;
        if (lane < m){
            idx = g_eid[jb + lane];
            src = (idx < E_) ? ei[idx] : d;
        }
#pragma unroll 1
        for (int jj = 0; jj < m; ++jj){
            int eidx = __shfl_sync(0xffffffffu, idx, jj);
            int esrc = __shfl_sync(0xffffffffu, src, jj);
            float4 e4 = *(const float4*)(g_efull + (size_t)eidx*4);
            float4 a4 = *(const float4*)(g_xl + (size_t)esrc*DD + c0);
            float av[4] = {a4.x, a4.y, a4.z, a4.w};
            float bv[4] = {b4.x, b4.y, b4.z, b4.w};
            float p = 0.f;
#pragma unroll
            for (int j = 0; j < 4; ++j){
                int c = c0 + j;
                float ee = e4.x*sWe[c] + e4.y*sWe[DD + c]
                         + e4.z*sWe[2*DD + c] + e4.w*sWe[3*DD + c];
                float g = av[j] + bv[j] + ee;
                g = (g > 0.f) ? g : 0.2f*g;
                p += g * sAtt[c];
            }
            p += __shfl_xor_sync(0xffffffffu, p, 1);
            p += __shfl_xor_sync(0xffffffffu, p, 2);
            p += __shfl_xor_sync(0xffffffffu, p, 4);
            float w = 0.f;
            if ((lane & 7) == 0){
                w = expf(p);
                zacc += w;
            }
            w = __shfl_sync(0xffffffffu, w, lane & 24);
            acc0 += av[0]*w; acc1 += av[1]*w; acc2 += av[2]*w; acc3 += av[3]*w;
        }
    }

    float z = __shfl_sync(0xffffffffu, zacc, lane & 24);
    float inv = 1.0f / (z + 1e-16f);
    float4 o;
    o.x = acc0*inv + sCb[c0];
    o.y = acc1*inv + sCb[c0+1];
    o.z = acc2*inv + sCb[c0+2];
    o.w = acc3*inv + sCb[c0+3];

    if (last){
        *(float4*)(g_h + (size_t)d*DD + c0) = o;
        return;
    }
    // relu
    o.x = fmaxf(o.x, 0.f); o.y = fmaxf(o.y, 0.f);
    o.z = fmaxf(o.z, 0.f); o.w = fmaxf(o.w, 0.f);
    // quantize row to int8 hi+lo
    float mx = fmaxf(fmaxf(o.x, o.y), fmaxf(o.z, o.w));
#pragma unroll
    for (int off = 16; off > 0; off >>= 1)
        mx = fmaxf(mx, __shfl_xor_sync(0xffffffffu, mx, off));
    float sa = fmaxf(mx, 1e-20f) * (1.0f/127.0f);
    float is = 1.0f / sa;
    float qv[4] = {o.x*is, o.y*is, o.z*is, o.w*is};
    uint hiu = 0, lou = 0;
#pragma unroll
    for (int j = 0; j < 4; ++j){
        int hi = q8(qv[j]);
        int lo = q8((qv[j] - (float)hi) * 256.0f);
        hiu |= (uint)(hi & 255) << (8*j);
        lou |= (uint)(lo & 255) << (8*j);
    }
    g_hq[(size_t)d*64 + lane]      = hiu;
    g_hq[(size_t)d*64 + 32 + lane] = lou;
    if (lane == 0) g_hs[d] = sa;
}

// ---------------- head ----------------
__global__ void k_head(float* out, const float* __restrict__ bout, int G){
    int g = blockIdx.x*blockDim.x + threadIdx.x;
    if (g < G) out[g] = bout[0];
}

__global__ void k_pool(const float* __restrict__ Wout, const int* __restrict__ bid,
                       float* out, int n){
    int gw   = blockIdx.x*8 + (threadIdx.x >> 5);
    int lane = threadIdx.x & 31;
    if (gw >= n) return;
    float4 hv = *(const float4*)(g_h + (size_t)gw*DD + lane*4);
    float4 wv = *(const float4*)(Wout + lane*4);
    float p = hv.x*wv.x + hv.y*wv.y + hv.z*wv.z + hv.w*wv.w;
#pragma unroll
    for (int o = 16; o > 0; o >>= 1) p += __shfl_xor_sync(0xffffffffu, p, o);
    if (lane == 0) atomicAdd(out + bid[gw], p);
}

// ---------------- launch ----------------
extern "C" void kernel_launch(void* const* d_in, const int* in_sizes, int n_in,
                              void* d_out, int out_size){
    const float* atab = (const float*)d_in[0];
    const float* bond = (const float*)d_in[1];
    const float* Wl   = (const float*)d_in[2];
    const float* bl   = (const float*)d_in[3];
    const float* Wr   = (const float*)d_in[4];
    const float* br   = (const float*)d_in[5];
    const float* We   = (const float*)d_in[6];
    const float* att  = (const float*)d_in[7];
    const float* cb   = (const float*)d_in[8];
    const float* Wout = (const float*)d_in[9];
    const float* bout = (const float*)d_in[10];
    const int*   x    = (const int*)d_in[11];
    const int*   ei   = (const int*)d_in[12];
    const int*   ea   = (const int*)d_in[13];
    const int*   bid  = (const int*)d_in[14];

    int n  = in_sizes[11] / 9;
    int E_ = in_sizes[13];
    int G  = out_size;
    float* out = (float*)d_out;

    const int SMEM = (64*SAU*2 + 256*SAU*2)*4 + 512*4;  // ~94 KB
    cudaFuncSetAttribute(k_tc, cudaFuncAttributeMaxDynamicSharedMemorySize, SMEM);

    int nb = (n + 255)/256;
    int nsb = (n + 1023)/1024;
    int M  = E_ + n;

    k_atom<<<n, 128>>>(atab, x, n);
    k_zero<<<nb, 256>>>(n);
    k_edge<<<(E_ + 255)/256, 256>>>(bond, ei, ea, E_);
    k_self<<<nb, 256>>>(E_, n);

    // CSR build
    k_scan1<<<nsb, 256>>>(n);
    k_scan2<<<1, 1>>>(nsb);
    k_scan3<<<nb, 256>>>(n, nsb);
    k_scatter<<<(M + 255)/256, 256>>>(ei, E_, n);

    for (int l = 0; l < 4; ++l){
        k_tc<<<GDIM, 256, SMEM>>>(Wl + l*DD*DD, bl + l*DD, Wr + l*DD*DD, br + l*DD, n);
        k_att2<<<(n + 7)/8, 256>>>(ei, We + l*4*DD, att + l*DD, cb + l*DD,
                                   E_, n, (l == 3) ? 1 : 0);
    }

    k_head<<<(G + 255)/256, 256>>>(out, bout, G);
    k_pool<<<(n + 7)/8, 256>>>(Wout, bid, out, n);
}

// round 7
// speedup vs baseline: 1.4304x; 1.4304x over previous
#include <cuda_runtime.h>
#include <cuda_bf16.h>
#include <cstdint>

#define NMAX 200000
#define EMAX 400000
#define DD 128
#define HH 4
#define GDIM 148

typedef unsigned int uint;

// ---------------- scratch (device globals; no allocation) ----------------
__device__ __align__(16) float g_h[NMAX*DD];      // final-layer h (for pool)
__device__ __align__(16) uint  g_hq[NMAX*DD];     // h as bf16 split: per kpair {hi2, lo2}
__device__ __align__(16) float g_xl[NMAX*DD];
__device__ __align__(16) float g_xr[NMAX*DD];
__device__ __align__(16) float g_efull[(EMAX+NMAX)*HH];
__device__ __align__(16) float g_sums[NMAX*HH];
__device__ int g_deg[NMAX];
__device__ int g_off[NMAX+1];
__device__ int g_cur[NMAX];
__device__ int g_eid[EMAX+NMAX];
__device__ int g_bsum[260];

__device__ __forceinline__ void red4(float* p, float a, float b, float c, float d){
    asm volatile("red.global.add.v4.f32 [%0], {%1,%2,%3,%4};"
                 :: "l"(p), "f"(a), "f"(b), "f"(c), "f"(d) : "memory");
}

// split a pair of floats into bf16x2 (hi) + bf16x2 (lo residual)
__device__ __forceinline__ uint2 split2(float x0, float x1){
    __nv_bfloat162 h = __floats2bfloat162_rn(x0, x1);
    float r0 = x0 - __bfloat162float(h.x);
    float r1 = x1 - __bfloat162float(h.y);
    __nv_bfloat162 l = __floats2bfloat162_rn(r0, r1);
    uint2 u;
    u.x = *reinterpret_cast<uint32_t*>(&h);
    u.y = *reinterpret_cast<uint32_t*>(&l);
    return u;
}

// ---------------- atom encoder + bf16-split store ----------------
__global__ void k_atom(const float* __restrict__ tab, const int* __restrict__ x, int n){
    int i = blockIdx.x;
    int d = threadIdx.x;        // 128 threads
    __shared__ int xf[9];
    if (d < 9) xf[d] = x[i*9 + d];
    __syncthreads();
    float s = 0.f;
#pragma unroll
    for (int f = 0; f < 9; ++f)
        s += tab[(f*16 + xf[f])*DD + d];
    float s1 = __shfl_down_sync(0xffffffffu, s, 1);
    if ((d & 1) == 0){
        int kp = d >> 1;
        ((uint2*)(g_hq + (size_t)i*DD))[kp] = split2(s, s1);
    }
}

__global__ void k_zero(int n){
    int i = blockIdx.x*blockDim.x + threadIdx.x;
    if (i >= n) return;
    g_deg[i] = 0;
    *(float4*)(g_sums + i*4) = make_float4(0.f,0.f,0.f,0.f);
}

__global__ void k_edge(const float* __restrict__ bond, const int* __restrict__ ei,
                       const int* __restrict__ ea, int E_){
    int e = blockIdx.x*blockDim.x + threadIdx.x;
    if (e >= E_) return;
    int tt  = ea[e];
    int dst = ei[E_ + e];
    float4 b = *(const float4*)(bond + tt*4);
    *(float4*)(g_efull + e*4) = b;
    red4(g_sums + dst*4, b.x, b.y, b.z, b.w);
    atomicAdd(g_deg + dst, 1);
}

__global__ void k_self(int E_, int n){
    int i = blockIdx.x*blockDim.x + threadIdx.x;
    if (i >= n) return;
    float inv = 1.0f / fmaxf((float)g_deg[i], 1.0f);
    float4 s = *(const float4*)(g_sums + i*4);
    *(float4*)(g_efull + (E_ + i)*4) = make_float4(s.x*inv, s.y*inv, s.z*inv, s.w*inv);
}

// ---------------- CSR build ----------------
__global__ void k_scan1(int n){
    __shared__ int ws[8];
    int t = threadIdx.x, b = blockIdx.x;
    int base = b*1024 + t*4;
    int v[4];
#pragma unroll
    for (int j = 0; j < 4; ++j){
        int i = base + j;
        v[j] = (i < n) ? (g_deg[i] + 1) : 0;
    }
    int s = v[0] + v[1] + v[2] + v[3];
    int lane = t & 31, wid = t >> 5;
    int x = s;
#pragma unroll
    for (int o = 1; o < 32; o <<= 1){
        int y = __shfl_up_sync(0xffffffffu, x, o);
        if (lane >= o) x += y;
    }
    if (lane == 31) ws[wid] = x;
    __syncthreads();
    if (t == 0){
        int r = 0;
#pragma unroll
        for (int w = 0; w < 8; ++w){ int tmp = ws[w]; ws[w] = r; r += tmp; }
        g_bsum[b] = r;
    }
    __syncthreads();
    int run = x - s + ws[wid];
#pragma unroll
    for (int j = 0; j < 4; ++j){
        int i = base + j;
        if (i < n) g_off[i] = run;
        run += v[j];
    }
}

__global__ void k_scan2(int nb){
    int r = 0;
    for (int b = 0; b < nb; ++b){ int t = g_bsum[b]; g_bsum[b] = r; r += t; }
    g_bsum[nb] = r;
}

__global__ void k_scan3(int n, int nb){
    int i = blockIdx.x*blockDim.x + threadIdx.x;
    if (i == 0) g_off[n] = g_bsum[nb];
    if (i >= n) return;
    int o = g_off[i] + g_bsum[i >> 10];
    g_off[i] = o;
    g_cur[i] = o;
}

__global__ void k_scatter(const int* __restrict__ ei, int E_, int n){
    int e = blockIdx.x*blockDim.x + threadIdx.x;
    if (e >= E_ + n) return;
    int dst = (e < E_) ? ei[E_ + e] : (e - E_);
    int pos = atomicAdd(g_cur + dst, 1);
    g_eid[pos] = e;
}

// ---------------- bf16-split dual GEMM: [xl|xr] = h @ [Wl|Wr] + bias ----------------
// A pre-split in g_hq (pure copies into smem); B built from W with split2.
// 3 MMA terms (hh, hl, lh). mma.sync m16n8k16.bf16, CTA tile 64x256, 8 warps 2x4.
#define SAST 66   // uint2 row stride
#define MMA3(acc, ah, al, bh0, bh1, bl0, bl1) do { \
    asm volatile("mma.sync.aligned.m16n8k16.row.col.f32.bf16.bf16.f32 " \
        "{%0,%1,%2,%3}, {%4,%5,%6,%7}, {%8,%9}, {%0,%1,%2,%3};" \
        : "+f"(acc[0]), "+f"(acc[1]), "+f"(acc[2]), "+f"(acc[3]) \
        : "r"(ah[0]), "r"(ah[1]), "r"(ah[2]), "r"(ah[3]), "r"(bh0), "r"(bh1)); \
    asm volatile("mma.sync.aligned.m16n8k16.row.col.f32.bf16.bf16.f32 " \
        "{%0,%1,%2,%3}, {%4,%5,%6,%7}, {%8,%9}, {%0,%1,%2,%3};" \
        : "+f"(acc[0]), "+f"(acc[1]), "+f"(acc[2]), "+f"(acc[3]) \
        : "r"(ah[0]), "r"(ah[1]), "r"(ah[2]), "r"(ah[3]), "r"(bl0), "r"(bl1)); \
    asm volatile("mma.sync.aligned.m16n8k16.row.col.f32.bf16.bf16.f32 " \
        "{%0,%1,%2,%3}, {%4,%5,%6,%7}, {%8,%9}, {%0,%1,%2,%3};" \
        : "+f"(acc[0]), "+f"(acc[1]), "+f"(acc[2]), "+f"(acc[3]) \
        : "r"(al[0]), "r"(al[1]), "r"(al[2]), "r"(al[3]), "r"(bh0), "r"(bh1)); \
} while(0)

__global__ __launch_bounds__(256, 1)
void k_tc(const float* __restrict__ Wl, const float* __restrict__ bl,
          const float* __restrict__ Wr, const float* __restrict__ br, int n){
    extern __shared__ uint2 smu[];
    uint2* sB = smu;                   // [256][SAST]
    uint2* sA = smu + 256*SAST;        // [64][SAST]
    float* sBias = (float*)(smu + 256*SAST + 64*SAST);  // [256]
    int tid = threadIdx.x, wid = tid >> 5, lane = tid & 31;
    int gq = lane >> 2, tg = lane & 3;
    int wm = wid & 1, wn = wid >> 1;

    // build B = [Wl^T ; Wr^T] (coalesced over c)
    for (int idx = tid; idx < 256*64; idx += 256){
        int c = idx & 255, kp = idx >> 8;
        int k = kp*2;
        float w0, w1;
        if (c < 128){ w0 = Wl[k*DD + c];        w1 = Wl[(k+1)*DD + c]; }
        else        { w0 = Wr[k*DD + (c-128)];  w1 = Wr[(k+1)*DD + (c-128)]; }
        sB[c*SAST + kp] = split2(w0, w1);
    }
    sBias[tid] = (tid < 128) ? bl[tid] : br[tid - 128];

    int tiles = (n + 63) >> 6;
    uint4 pre[8];
    {
        int base = blockIdx.x * 64;
#pragma unroll
        for (int r = 0; r < 8; ++r){
            int j = r*256 + tid;
            int node = j >> 5, p = j & 31;
            int gn = base + node;
            pre[r] = (gn < n) ? *(const uint4*)(g_hq + (size_t)gn*DD + p*4)
                              : make_uint4(0u,0u,0u,0u);
        }
    }

    for (int tile = blockIdx.x; tile < tiles; tile += GDIM){
        __syncthreads();
#pragma unroll
        for (int r = 0; r < 8; ++r){
            int j = r*256 + tid;
            int node = j >> 5, p = j & 31;
            *(uint4*)(sA + node*SAST + p*2) = pre[r];
        }
        __syncthreads();
        if (tile + GDIM < tiles){
            int base = (tile + GDIM) * 64;
#pragma unroll
            for (int r = 0; r < 8; ++r){
                int j = r*256 + tid;
                int node = j >> 5, p = j & 31;
                int gn = base + node;
                pre[r] = (gn < n) ? *(const uint4*)(g_hq + (size_t)gn*DD + p*4)
                                  : make_uint4(0u,0u,0u,0u);
            }
        }

        float acc[2][8][4];
#pragma unroll
        for (int mb = 0; mb < 2; ++mb)
#pragma unroll
            for (int nb = 0; nb < 8; ++nb)
#pragma unroll
                for (int j = 0; j < 4; ++j) acc[mb][nb][j] = 0.f;

#pragma unroll 2
        for (int kc = 0; kc < 8; ++kc){
            int kp0 = kc*8 + tg;
            uint32_t ah[2][4], al[2][4];
#pragma unroll
            for (int mb = 0; mb < 2; ++mb){
                int r0 = wm*32 + mb*16 + gq;
                uint2 p0 = sA[r0*SAST + kp0];
                uint2 p1 = sA[(r0+8)*SAST + kp0];
                uint2 p2 = sA[r0*SAST + kp0 + 4];
                uint2 p3 = sA[(r0+8)*SAST + kp0 + 4];
                ah[mb][0] = p0.x; ah[mb][1] = p1.x; ah[mb][2] = p2.x; ah[mb][3] = p3.x;
                al[mb][0] = p0.y; al[mb][1] = p1.y; al[mb][2] = p2.y; al[mb][3] = p3.y;
            }
#pragma unroll
            for (int nb = 0; nb < 8; ++nb){
                int col = wn*64 + nb*8 + gq;
                uint2 pb0 = sB[col*SAST + kp0];
                uint2 pb1 = sB[col*SAST + kp0 + 4];
#pragma unroll
                for (int mb = 0; mb < 2; ++mb)
                    MMA3(acc[mb][nb], ah[mb], al[mb], pb0.x, pb1.x, pb0.y, pb1.y);
            }
        }

        int base = tile*64;
#pragma unroll
        for (int mb = 0; mb < 2; ++mb){
            int gm0 = base + wm*32 + mb*16 + gq;
            int gm1 = gm0 + 8;
#pragma unroll
            for (int nb = 0; nb < 8; ++nb){
                int c0 = wn*64 + nb*8 + tg*2;
                float bx = sBias[c0], by = sBias[c0 + 1];
                float* outp = (c0 < 128) ? g_xl : g_xr;
                int cl = (c0 < 128) ? c0 : c0 - 128;
                if (gm0 < n)
                    *(float2*)(outp + (size_t)gm0*DD + cl)
                        = make_float2(acc[mb][nb][0] + bx, acc[mb][nb][1] + by);
                if (gm1 < n)
                    *(float2*)(outp + (size_t)gm1*DD + cl)
                        = make_float2(acc[mb][nb][2] + bx, acc[mb][nb][3] + by);
            }
        }
    }
}

// ---------------- CSR fused edge pass + normalize + bias + relu + split-store ----------------
__global__ void k_att2(const int* __restrict__ ei, const float* __restrict__ We,
                       const float* __restrict__ att, const float* __restrict__ cb,
                       int E_, int n, int last){
    __shared__ float sWe[4*DD];
    __shared__ float sAtt[DD];
    __shared__ float sCb[DD];
    int t = threadIdx.x;
    for (int i = t; i < 4*DD; i += 256) sWe[i] = We[i];
    if (t < DD){ sAtt[t] = att[t]; sCb[t] = cb[t]; }
    __syncthreads();

    int d = blockIdx.x*8 + (t >> 5);
    if (d >= n) return;
    int lane = t & 31;
    int off0 = g_off[d], off1 = g_off[d+1];
    int c0 = lane*4;

    float4 b4 = *(const float4*)(g_xr + (size_t)d*DD + c0);
    float acc0 = 0.f, acc1 = 0.f, acc2 = 0.f, acc3 = 0.f;
    float zacc = 0.f;

    for (int jb = off0; jb < off1; jb += 32){
        int m = min(32, off1 - jb);
        int idx = 0, src = d;
        if (lane < m){
            idx = g_eid[jb + lane];
            src = (idx < E_) ? ei[idx] : d;
        }
#pragma unroll 1
        for (int jj = 0; jj < m; ++jj){
            int eidx = __shfl_sync(0xffffffffu, idx, jj);
            int esrc = __shfl_sync(0xffffffffu, src, jj);
            float4 e4 = *(const float4*)(g_efull + (size_t)eidx*4);
            float4 a4 = *(const float4*)(g_xl + (size_t)esrc*DD + c0);
            float av[4] = {a4.x, a4.y, a4.z, a4.w};
            float bv[4] = {b4.x, b4.y, b4.z, b4.w};
            float p = 0.f;
#pragma unroll
            for (int j = 0; j < 4; ++j){
                int c = c0 + j;
                float ee = e4.x*sWe[c] + e4.y*sWe[DD + c]
                         + e4.z*sWe[2*DD + c] + e4.w*sWe[3*DD + c];
                float g = av[j] + bv[j] + ee;
                g = (g > 0.f) ? g : 0.2f*g;
                p += g * sAtt[c];
            }
            p += __shfl_xor_sync(0xffffffffu, p, 1);
            p += __shfl_xor_sync(0xffffffffu, p, 2);
            p += __shfl_xor_sync(0xffffffffu, p, 4);
            float w = 0.f;
            if ((lane & 7) == 0){
                w = expf(p);
                zacc += w;
            }
            w = __shfl_sync(0xffffffffu, w, lane & 24);
            acc0 += av[0]*w; acc1 += av[1]*w; acc2 += av[2]*w; acc3 += av[3]*w;
        }
    }

    float z = __shfl_sync(0xffffffffu, zacc, lane & 24);
    float inv = 1.0f / (z + 1e-16f);
    float4 o;
    o.x = acc0*inv + sCb[c0];
    o.y = acc1*inv + sCb[c0+1];
    o.z = acc2*inv + sCb[c0+2];
    o.w = acc3*inv + sCb[c0+3];

    if (last){
        *(float4*)(g_h + (size_t)d*DD + c0) = o;
        return;
    }
    o.x = fmaxf(o.x, 0.f); o.y = fmaxf(o.y, 0.f);
    o.z = fmaxf(o.z, 0.f); o.w = fmaxf(o.w, 0.f);
    uint2 u0 = split2(o.x, o.y);
    uint2 u1 = split2(o.z, o.w);
    *(uint4*)(g_hq + (size_t)d*DD + lane*4) = make_uint4(u0.x, u0.y, u1.x, u1.y);
}

// ---------------- head ----------------
__global__ void k_head(float* out, const float* __restrict__ bout, int G){
    int g = blockIdx.x*blockDim.x + threadIdx.x;
    if (g < G) out[g] = bout[0];
}

__global__ void k_pool(const float* __restrict__ Wout, const int* __restrict__ bid,
                       float* out, int n){
    int gw   = blockIdx.x*8 + (threadIdx.x >> 5);
    int lane = threadIdx.x & 31;
    if (gw >= n) return;
    float4 hv = *(const float4*)(g_h + (size_t)gw*DD + lane*4);
    float4 wv = *(const float4*)(Wout + lane*4);
    float p = hv.x*wv.x + hv.y*wv.y + hv.z*wv.z + hv.w*wv.w;
#pragma unroll
    for (int o = 16; o > 0; o >>= 1) p += __shfl_xor_sync(0xffffffffu, p, o);
    if (lane == 0) atomicAdd(out + bid[gw], p);
}

// ---------------- launch ----------------
extern "C" void kernel_launch(void* const* d_in, const int* in_sizes, int n_in,
                              void* d_out, int out_size){
    const float* atab = (const float*)d_in[0];
    const float* bond = (const float*)d_in[1];
    const float* Wl   = (const float*)d_in[2];
    const float* bl   = (const float*)d_in[3];
    const float* Wr   = (const float*)d_in[4];
    const float* br   = (const float*)d_in[5];
    const float* We   = (const float*)d_in[6];
    const float* att  = (const float*)d_in[7];
    const float* cb   = (const float*)d_in[8];
    const float* Wout = (const float*)d_in[9];
    const float* bout = (const float*)d_in[10];
    const int*   x    = (const int*)d_in[11];
    const int*   ei   = (const int*)d_in[12];
    const int*   ea   = (const int*)d_in[13];
    const int*   bid  = (const int*)d_in[14];

    int n  = in_sizes[11] / 9;
    int E_ = in_sizes[13];
    int G  = out_size;
    float* out = (float*)d_out;

    const int SMEM = (256*SAST + 64*SAST)*8 + 256*4;   // ~170 KB
    cudaFuncSetAttribute(k_tc, cudaFuncAttributeMaxDynamicSharedMemorySize, SMEM);

    int nb = (n + 255)/256;
    int nsb = (n + 1023)/1024;
    int M  = E_ + n;

    k_atom<<<n, 128>>>(atab, x, n);                                   // 0
    k_zero<<<nb, 256>>>(n);                                           // 1
    k_edge<<<(E_ + 255)/256, 256>>>(bond, ei, ea, E_);                // 2
    k_tc<<<GDIM, 256, SMEM>>>(Wl, bl, Wr, br, n);                     // 3 (ncu window)
    k_self<<<nb, 256>>>(E_, n);                                       // 4
    k_scan1<<<nsb, 256>>>(n);
    k_scan2<<<1, 1>>>(nsb);
    k_scan3<<<nb, 256>>>(n, nsb);
    k_scatter<<<(M + 255)/256, 256>>>(ei, E_, n);
    k_att2<<<(n + 7)/8, 256>>>(ei, We, att, cb, E_, n, 0);

    for (int l = 1; l < 4; ++l){
        k_tc<<<GDIM, 256, SMEM>>>(Wl + l*DD*DD, bl + l*DD, Wr + l*DD*DD, br + l*DD, n);
        k_att2<<<(n + 7)/8, 256>>>(ei, We + l*4*DD, att + l*DD, cb + l*DD,
                                   E_, n, (l == 3) ? 1 : 0);
    }

    k_head<<<(G + 255)/256, 256>>>(out, bout, G);
    k_pool<<<(n + 7)/8, 256>>>(Wout, bid, out, n);
}